// round 14
// baseline (speedup 1.0000x reference)
#include <cuda_runtime.h>
#include <cuda_bf16.h>
#include <cstdint>

#define BATCH 2048
#define RPB   8        // rows per MLP CTA (M tile = 16, rows 8..15 zero)
#define NCTA  256
#define NTHR  256      // 8 warps, each owns a 16-col N-slice
#define XCOLS 39
#define HID   128
#define WP    272      // act smem pitch bytes (136 bf16)

// ---- smem byte offsets ----
#define E_H 0          // emb A hi [16][WP]
#define E_L 4352
#define AAH 8704       // actA
#define AAL 13056
#define ABH 17408      // actB
#define ABL 21760
#define OW2 26112      // wc2bar [128][8] f32 (4096)
#define OB1 30208      // bf1 [128]
#define OB2 30720      // bf2
#define OB3 31232      // bc1
#define OB4 31744      // bb1
#define OWB 32256      // Wb2
#define OBC 32768      // bc2bar[6], [6]=bb2 (32B)
#define OSB 32800      // sbase [8] (32B)
#define OCF 32832      // coefB [8][4][4] (512B)
#define OPC 33344      // cbar partials [8w][8row][6] (1536B)
#define OPB 34880      // sbase partials [8w][8row] (256B)
#define OIX 35136      // x categorical idx [8][3] int (96B)
#define MLP_SMEM 35232

// weights preconverted into mma.sync B-fragment order:
// idx = ((m*8 + K)*16 + slice)*32 + lane ; uint4 = {bh0, bh1, bl0, bl1}
__device__ uint4 g_bfrag[4 * 8 * 16 * 32];

// ---------------- PTX wrappers ----------------
__device__ __forceinline__ void ldm4(uint32_t r[4], uint32_t a) {
    asm volatile("ldmatrix.sync.aligned.m8n8.x4.shared.b16 {%0,%1,%2,%3}, [%4];"
                 : "=r"(r[0]), "=r"(r[1]), "=r"(r[2]), "=r"(r[3]) : "r"(a));
}
__device__ __forceinline__ void mma_bf16(float d[4], const uint32_t a[4],
                                         uint32_t b0, uint32_t b1) {
    asm("mma.sync.aligned.m16n8k16.row.col.f32.bf16.bf16.f32 "
        "{%0,%1,%2,%3}, {%4,%5,%6,%7}, {%8,%9}, {%0,%1,%2,%3};"
        : "+f"(d[0]), "+f"(d[1]), "+f"(d[2]), "+f"(d[3])
        : "r"(a[0]), "r"(a[1]), "r"(a[2]), "r"(a[3]), "r"(b0), "r"(b1));
}
__device__ __forceinline__ void split2(float v0, float v1, uint32_t& hi, uint32_t& lo) {
    __nv_bfloat162 h = __floats2bfloat162_rn(v0, v1);
    float f0 = __bfloat162float(h.x), f1 = __bfloat162float(h.y);
    __nv_bfloat162 g = __floats2bfloat162_rn(v0 - f0, v1 - f1);
    hi = *reinterpret_cast<uint32_t*>(&h);
    lo = *reinterpret_cast<uint32_t*>(&g);
}

// ---------------- fast convert: 32 blocks, coalesced load + smem transpose ----
// FIX vs R13: each thread emits TWO fragments (slices s and s+8) — all 16 slices.
__global__ __launch_bounds__(256) void convert_kernel(
    const float* __restrict__ Wf1, const float* __restrict__ Wf2,
    const float* __restrict__ Wc1, const float* __restrict__ Wb1)
{
    __shared__ float ws[16][132];   // padded: bank-conflict-free fragment reads
    int b = blockIdx.x;
    int m = b >> 3, K = b & 7;
    int tid = threadIdx.x;
    const float* src = (m == 0) ? Wf1 : (m == 1) ? Wf2 : (m == 2) ? Wc1 : Wb1;

    // load 16 rows x 128 cols fp32, fully coalesced (2 float4/thread)
    #pragma unroll
    for (int i = 0; i < 2; i++) {
        int e = tid + i * 256;
        int r = e >> 5, c4 = e & 31;
        int gr = K * 16 + r;
        float4 v = make_float4(0.f, 0.f, 0.f, 0.f);
        if (m != 0 || gr < 68) v = ((const float4*)src)[gr * 32 + c4];
        *(float4*)&ws[r][c4 * 4] = v;
    }
    __syncthreads();

    // two fragment uint4 per thread (slices s and s+8)
    int lane = tid & 31, s = tid >> 5;
    int ql = lane & 3, gid = lane >> 2;
    int k0 = 2 * ql;
    #pragma unroll
    for (int h = 0; h < 2; h++) {
        int ss = s + h * 8;
        int n = ss * 8 + gid;
        float v0 = ws[k0][n],     v1 = ws[k0 + 1][n];
        float v2 = ws[k0 + 8][n], v3 = ws[k0 + 9][n];
        uint32_t bh0, bl0, bh1, bl1;
        split2(v0, v1, bh0, bl0);
        split2(v2, v3, bh1, bl1);
        g_bfrag[((m * 8 + K) * 16 + ss) * 32 + lane] = make_uint4(bh0, bh1, bl0, bl1);
    }
}

// one layer over a 16-col slice: B frags direct from global, pipelined 1 kstep ahead
template<int KS>
__device__ __forceinline__ void mma_layer2(float a0[3][4], float a1[3][4],
                                           uint32_t aH, uint32_t aL,
                                           const uint4* __restrict__ frag,
                                           int lr, int lc)
{
    uint4 b0 = frag[0], b1 = frag[32];
    uint32_t base = (uint32_t)(lr * WP + lc * 2);
    #pragma unroll
    for (int K = 0; K < KS; K++) {
        uint4 n0, n1;
        if (K + 1 < KS) { n0 = frag[(K + 1) * 512]; n1 = frag[(K + 1) * 512 + 32]; }
        uint32_t ah[4], al[4];
        ldm4(ah, aH + base + K * 32);
        ldm4(al, aL + base + K * 32);
        mma_bf16(a0[0], ah, b0.x, b0.y);
        mma_bf16(a0[1], ah, b0.z, b0.w);
        mma_bf16(a0[2], al, b0.x, b0.y);
        mma_bf16(a1[0], ah, b1.x, b1.y);
        mma_bf16(a1[1], ah, b1.z, b1.w);
        mma_bf16(a1[2], al, b1.x, b1.y);
        b0 = n0; b1 = n1;
    }
}

#define RESET_ACC(a) do { \
    _Pragma("unroll") \
    for (int p = 0; p < 3; p++) (a)[p][0] = (a)[p][1] = (a)[p][2] = (a)[p][3] = 0.f; \
} while (0)

// bias+relu -> bf16 hi/lo act buffer (16-col slice, real row r0 only)
__device__ __forceinline__ void epi_act(float a0[3][4], float a1[3][4],
                                        const float* __restrict__ bias,
                                        char* smem, int offH, int offL,
                                        int w, int lane)
{
    int r0 = lane >> 2, ql = lane & 3;
    int c = w * 16 + 2 * ql;
    float2 bA = *(const float2*)(bias + c);
    float2 bB = *(const float2*)(bias + c + 8);
    float v0 = fmaxf(a0[0][0] + a0[1][0] + a0[2][0] + bA.x, 0.f);
    float v1 = fmaxf(a0[0][1] + a0[1][1] + a0[2][1] + bA.y, 0.f);
    float u0 = fmaxf(a1[0][0] + a1[1][0] + a1[2][0] + bB.x, 0.f);
    float u1 = fmaxf(a1[0][1] + a1[1][1] + a1[2][1] + bB.y, 0.f);
    uint32_t h0, l0, h1, l1;
    split2(v0, v1, h0, l0);
    split2(u0, u1, h1, l1);
    *(uint32_t*)(smem + offH + r0 * WP + c * 2)       = h0;
    *(uint32_t*)(smem + offL + r0 * WP + c * 2)       = l0;
    *(uint32_t*)(smem + offH + r0 * WP + (c + 8) * 2) = h1;
    *(uint32_t*)(smem + offL + r0 * WP + (c + 8) * 2) = l1;
    RESET_ACC(a0); RESET_ACC(a1);
}

__global__ __launch_bounds__(NTHR, 2) void mlp_kernel(
    const float* __restrict__ x,
    const float* __restrict__ budget,
    const float* __restrict__ emb_id, const float* __restrict__ emb_period,
    const float* __restrict__ emb_time,
    const float* __restrict__ bf1, const float* __restrict__ bf2,
    const float* __restrict__ bc1, const float* __restrict__ Wc2,
    const float* __restrict__ bc2,
    const float* __restrict__ bb1, const float* __restrict__ Wb2,
    const float* __restrict__ bb2,
    float* __restrict__ out)
{
    extern __shared__ char smem[];
    float* smf = (float*)smem;
    const int tid  = threadIdx.x;
    const int w    = tid >> 5;
    const int lane = tid & 31;
    const int lr   = lane & 15;
    const int lc   = (lane >> 4) * 8;
    const int r0l  = lane >> 2;
    const int ql   = lane & 3;
    const int row0 = blockIdx.x * RPB;
    const uint32_t smb = (uint32_t)__cvta_generic_to_shared(smem);
    const uint4* fragW = g_bfrag + (2 * w) * 32 + lane;   // + m*4096 per layer

    // ======== PDL-independent prologue (overlaps convert_kernel) ====
    if (tid < 24) {
        int r = tid / 3, c = tid - r * 3;
        ((int*)(smem + OIX))[r * 3 + c] = (int)x[(row0 + r) * XCOLS + c];
    }
    // budget prefetch -> registers
    const float4* bud4 = (const float4*)budget + row0 * 128;
    float4 pf[4];
    #pragma unroll
    for (int it = 0; it < 4; it++) pf[it] = bud4[tid + it * NTHR];

    // zero E/actA/actB hi+lo (1632 uint4) — guarantees rows 8..15 stay zero
    {
        uint4 z = make_uint4(0, 0, 0, 0);
        #pragma unroll
        for (int i = 0; i < 6; i++) ((uint4*)(smem + E_H))[tid + i * 256] = z;
        if (tid < 96) ((uint4*)(smem + E_H))[1536 + tid] = z;
    }

    // wc2bar from Wc2 (harness input — independent of convert)
    if (tid < 128) {
        float s[6] = {0, 0, 0, 0, 0, 0};
        const float4* w4 = (const float4*)(Wc2 + tid * 48);
        #pragma unroll
        for (int v = 0; v < 12; v++) {
            float4 f = w4[v];
            s[(v * 4 + 0) % 6] += f.x; s[(v * 4 + 1) % 6] += f.y;
            s[(v * 4 + 2) % 6] += f.z; s[(v * 4 + 3) % 6] += f.w;
        }
        #pragma unroll
        for (int k = 0; k < 6; k++) smf[OW2 / 4 + tid * 8 + k] = s[k] * 0.125f;
    } else {
        int t = tid - 128;
        smf[OB1 / 4 + t] = bf1[t];
        smf[OB2 / 4 + t] = bf2[t];
        smf[OB3 / 4 + t] = bc1[t];
        smf[OB4 / 4 + t] = bb1[t];
        smf[OWB / 4 + t] = Wb2[t];
        if (t < 6) {
            float s = 0.f;
            #pragma unroll
            for (int j = 0; j < 8; j++) s += bc2[j * 6 + t];
            smf[OBC / 4 + t] = s * 0.125f;
        } else if (t == 6) {
            smf[OBC / 4 + 6] = bb2[0];
        }
    }
    __syncthreads();   // zeros + OIX visible

    // emb fill: row = warp id (8 rows), cols lane, lane+32, lane+64
    {
        const int* ix = (const int*)(smem + OIX);
        int r = w;
        int i0 = ix[r * 3 + 0], i1 = ix[r * 3 + 1], i2 = ix[r * 3 + 2];
        #pragma unroll
        for (int jj = 0; jj < 3; jj++) {
            int c = lane + jj * 32;
            if (c < 68) {
                float v;
                if      (c < 8)  v = emb_id    [i1 * 8  + c];
                else if (c < 16) v = emb_period[i0 * 8  + (c - 8)];
                else if (c < 32) v = emb_time  [i2 * 16 + (c - 16)];
                else             v = x[(row0 + r) * XCOLS + 3 + (c - 32)];
                __nv_bfloat16 h = __float2bfloat16(v);
                __nv_bfloat16 l = __float2bfloat16(v - __bfloat162float(h));
                *(__nv_bfloat16*)(smem + E_H + r * WP + c * 2) = h;
                *(__nv_bfloat16*)(smem + E_L + r * WP + c * 2) = l;
            }
        }
    }
    __syncthreads();   // emb visible

    // ======== wait for fragment weights ========
    cudaGridDependencySynchronize();

    float a0[3][4], a1[3][4];
    RESET_ACC(a0); RESET_ACC(a1);

    // ---- L1: E x Wf1 -> actA ----
    mma_layer2<5>(a0, a1, smb + E_H, smb + E_L, fragW, lr, lc);
    epi_act(a0, a1, smf + OB1 / 4, smem, AAH, AAL, w, lane);
    __syncthreads();

    // ---- L2: actA x Wf2 -> actB ----
    mma_layer2<8>(a0, a1, smb + AAH, smb + AAL, fragW + 4096, lr, lc);
    epi_act(a0, a1, smf + OB2 / 4, smem, ABH, ABL, w, lane);
    __syncthreads();

    // ---- L3: actB x Wc1 -> cbar partials (fragment-direct) ----
    mma_layer2<8>(a0, a1, smb + ABH, smb + ABL, fragW + 2 * 4096, lr, lc);
    {
        int c = w * 16 + 2 * ql;
        float2 bA = *(const float2*)(smf + OB3 / 4 + c);
        float2 bB = *(const float2*)(smf + OB3 / 4 + c + 8);
        float v0 = fmaxf(a0[0][0] + a0[1][0] + a0[2][0] + bA.x, 0.f);
        float v1 = fmaxf(a0[0][1] + a0[1][1] + a0[2][1] + bA.y, 0.f);
        float u0 = fmaxf(a1[0][0] + a1[1][0] + a1[2][0] + bB.x, 0.f);
        float u1 = fmaxf(a1[0][1] + a1[1][1] + a1[2][1] + bB.y, 0.f);
        const float* w0p = smf + OW2 / 4 + c * 8;
        const float* w1p = w0p + 8;
        const float* w2p = smf + OW2 / 4 + (c + 8) * 8;
        const float* w3p = w2p + 8;
        float p[6];
        #pragma unroll
        for (int k = 0; k < 6; k++)
            p[k] = v0 * w0p[k] + v1 * w1p[k] + u0 * w2p[k] + u1 * w3p[k];
        #pragma unroll
        for (int k = 0; k < 6; k++) {
            p[k] += __shfl_xor_sync(0xffffffff, p[k], 1);
            p[k] += __shfl_xor_sync(0xffffffff, p[k], 2);
        }
        if (ql == 0) {
            float* d = smf + OPC / 4 + (w * 8 + r0l) * 6;
            #pragma unroll
            for (int k = 0; k < 6; k++) d[k] = p[k];
        }
        RESET_ACC(a0); RESET_ACC(a1);
    }
    // NO barrier: L4 re-reads the unchanged actB smem

    // ---- L4: actB x Wb1 -> sbase partials ----
    mma_layer2<8>(a0, a1, smb + ABH, smb + ABL, fragW + 3 * 4096, lr, lc);
    {
        int c = w * 16 + 2 * ql;
        float2 bA = *(const float2*)(smf + OB4 / 4 + c);
        float2 bB = *(const float2*)(smf + OB4 / 4 + c + 8);
        float2 wA = *(const float2*)(smf + OWB / 4 + c);
        float2 wB = *(const float2*)(smf + OWB / 4 + c + 8);
        float s = fmaxf(a0[0][0] + a0[1][0] + a0[2][0] + bA.x, 0.f) * wA.x
                + fmaxf(a0[0][1] + a0[1][1] + a0[2][1] + bA.y, 0.f) * wA.y
                + fmaxf(a1[0][0] + a1[1][0] + a1[2][0] + bB.x, 0.f) * wB.x
                + fmaxf(a1[0][1] + a1[1][1] + a1[2][1] + bB.y, 0.f) * wB.y;
        s += __shfl_xor_sync(0xffffffff, s, 1);
        s += __shfl_xor_sync(0xffffffff, s, 2);
        if (ql == 0) smf[OPB / 4 + w * 8 + r0l] = s;
    }
    __syncthreads();   // OPC + OPB visible

    // ---- fused combine + cubic (24 threads) + sbase combine (8 threads) ----
    if (tid < 24) {
        int rb = tid / 3, m = tid - rb * 3;
        float cb[4];
        #pragma unroll
        for (int j = 0; j < 4; j++) {
            float s = smf[OBC / 4 + m + j];
            #pragma unroll
            for (int ww = 0; ww < 8; ww++)
                s += smf[OPC / 4 + (ww * 8 + rb) * 6 + m + j];
            cb[j] = s;
        }
        float c0 = cb[0], c1 = cb[1], c2 = cb[2], c3 = cb[3];
        const float k6 = 1.f / 6.f;
        float A0 = (c0 + 4.f * c1 + c2) * k6;
        float A1 = (c2 - c0) * 0.5f;
        float A2 = (c0 - 2.f * c1 + c2) * 0.5f;
        float A3 = (c3 - c0 + 3.f * (c1 - c2)) * k6;
        float d  = 1.5f - (float)m;
        float B0 = A0 + d * (A1 + d * (A2 + d * A3));
        float B1 = 1.5f * (A1 + d * (2.f * A2 + 3.f * A3 * d));
        float B2 = 2.25f * (A2 + 3.f * A3 * d);
        float B3 = 3.375f * A3;
        ((float4*)(smem + OCF))[rb * 4 + m] = make_float4(B0, B1, B2, B3);
    } else if (tid < 32) {
        int rb = tid - 24;
        float s = smf[OBC / 4 + 6];
        #pragma unroll
        for (int ww = 0; ww < 8; ww++)
            s += smf[OPB / 4 + ww * 8 + rb];
        smf[OSB / 4 + rb] = s;
    }
    __syncthreads();

    // ---- budget phase: data already in pf[] registers ----
    float4* out4 = (float4*)out + row0 * 128;
    const float4* cb4 = (const float4*)(smem + OCF);
    #pragma unroll
    for (int it = 0; it < 4; it++) {
        int q = tid + it * NTHR;
        int row = q >> 7;
        float4 bv = pf[it];
        float sb = smf[OSB / 4 + row];
        float xs[4] = {bv.x, bv.y, bv.z, bv.w};
        float o[4];
        #pragma unroll
        for (int e = 0; e < 4; e++) {
            float X = xs[e];
            float tp = fmaf(X, 1.5f, 1.5f);
            int m = min((int)tp, 2);
            float4 B = cb4[row * 4 + m];
            float sp = fmaf(fmaf(fmaf(B.w, X, B.z), X, B.y), X, B.x);
            float u = X * X;
            float P = fmaf(u, fmaf(u, fmaf(u, fmaf(u, 2.1357286e-5f, -2.1081349e-4f),
                                           2.0833333e-3f), -2.0833333e-2f), 0.25f);
            float sil = X * fmaf(X, P, 0.5f);
            o[e] = sb * (sil + sp);
        }
        out4[q] = make_float4(o[0], o[1], o[2], o[3]);
    }
}

extern "C" void kernel_launch(void* const* d_in, const int* in_sizes, int n_in,
                              void* d_out, int out_size)
{
    const float* x          = (const float*)d_in[0];
    const float* budget     = (const float*)d_in[1];
    const float* emb_id     = (const float*)d_in[2];
    const float* emb_period = (const float*)d_in[3];
    const float* emb_time   = (const float*)d_in[4];
    const float* Wf1 = (const float*)d_in[5];
    const float* bf1 = (const float*)d_in[6];
    const float* Wf2 = (const float*)d_in[7];
    const float* bf2 = (const float*)d_in[8];
    const float* Wc1 = (const float*)d_in[9];
    const float* bc1 = (const float*)d_in[10];
    const float* Wc2 = (const float*)d_in[11];
    const float* bc2 = (const float*)d_in[12];
    // d_in[13..16] = Ws1/bs1/Ws2/bs2 : unused in reference output
    const float* Wb1 = (const float*)d_in[17];
    const float* bb1 = (const float*)d_in[18];
    const float* Wb2 = (const float*)d_in[19];
    const float* bb2 = (const float*)d_in[20];

    cudaFuncSetAttribute(mlp_kernel, cudaFuncAttributeMaxDynamicSharedMemorySize, MLP_SMEM);

    convert_kernel<<<32, 256>>>(Wf1, Wf2, Wc1, Wb1);

    // PDL launch: mlp starts while convert drains; prologue runs pre-sync
    cudaLaunchConfig_t cfg = {};
    cfg.gridDim = dim3(NCTA);
    cfg.blockDim = dim3(NTHR);
    cfg.dynamicSmemBytes = MLP_SMEM;
    cfg.stream = 0;
    cudaLaunchAttribute attrs[1];
    attrs[0].id = cudaLaunchAttributeProgrammaticStreamSerialization;
    attrs[0].val.programmaticStreamSerializationAllowed = 1;
    cfg.attrs = attrs;
    cfg.numAttrs = 1;
    cudaLaunchKernelEx(&cfg, mlp_kernel,
                       x, budget, emb_id, emb_period, emb_time,
                       bf1, bf2, bc1, Wc2, bc2, bb1, Wb2, bb2, (float*)d_out);
}

// round 15
// speedup vs baseline: 1.0985x; 1.0985x over previous
#include <cuda_runtime.h>
#include <cuda_bf16.h>
#include <cstdint>

#define BATCH 2048
#define RPB   16       // rows per MLP CTA
#define NCTA  128
#define NTHR  512      // 16 warps, each owns an 8-col N-slice
#define XCOLS 39
#define HID   128
#define WP    272      // act smem pitch bytes (136 bf16)

// ---- smem byte offsets ----
#define E_H 0          // emb A hi [16][WP]
#define E_L 4352
#define AAH 8704       // actA
#define AAL 13056
#define ABH 17408      // actB
#define ABL 21760
#define OW2 26112      // wc2bar [128][8] f32 (4096)
#define OB1 30208      // bf1 [128]
#define OB2 30720      // bf2
#define OB3 31232      // bc1
#define OB4 31744      // bb1
#define OWB 32256      // Wb2
#define OBC 32768      // bc2bar[6], [6]=bb2 (32B)
#define OSB 32800      // sbase [16] (64B)
#define OCF 32864      // coefB [16][4][4] (256B)
#define OPC 33120      // cbar partials [16w][16row][6] (6144B)
#define OPB 39264      // sbase partials [16w][16row] (1024B)
#define OIX 40288      // x categorical idx [16][3] int (192B)
#define MLP_SMEM 40480

// weights preconverted into mma.sync B-fragment order:
// idx = ((m*8 + K)*16 + slice)*32 + lane ; uint4 = {bh0, bh1, bl0, bl1}
__device__ uint4 g_bfrag[4 * 8 * 16 * 32];

// ---------------- PTX wrappers ----------------
__device__ __forceinline__ void ldm4(uint32_t r[4], uint32_t a) {
    asm volatile("ldmatrix.sync.aligned.m8n8.x4.shared.b16 {%0,%1,%2,%3}, [%4];"
                 : "=r"(r[0]), "=r"(r[1]), "=r"(r[2]), "=r"(r[3]) : "r"(a));
}
__device__ __forceinline__ void mma_bf16(float d[4], const uint32_t a[4],
                                         uint32_t b0, uint32_t b1) {
    asm("mma.sync.aligned.m16n8k16.row.col.f32.bf16.bf16.f32 "
        "{%0,%1,%2,%3}, {%4,%5,%6,%7}, {%8,%9}, {%0,%1,%2,%3};"
        : "+f"(d[0]), "+f"(d[1]), "+f"(d[2]), "+f"(d[3])
        : "r"(a[0]), "r"(a[1]), "r"(a[2]), "r"(a[3]), "r"(b0), "r"(b1));
}
__device__ __forceinline__ void split2(float v0, float v1, uint32_t& hi, uint32_t& lo) {
    __nv_bfloat162 h = __floats2bfloat162_rn(v0, v1);
    float f0 = __bfloat162float(h.x), f1 = __bfloat162float(h.y);
    __nv_bfloat162 g = __floats2bfloat162_rn(v0 - f0, v1 - f1);
    hi = *reinterpret_cast<uint32_t*>(&h);
    lo = *reinterpret_cast<uint32_t*>(&g);
}

// ---------------- fast convert: 32 blocks, coalesced load + smem transpose ----
// (benched correct in R14: each thread emits slices s and s+8)
__global__ __launch_bounds__(256) void convert_kernel(
    const float* __restrict__ Wf1, const float* __restrict__ Wf2,
    const float* __restrict__ Wc1, const float* __restrict__ Wb1)
{
    __shared__ float ws[16][132];   // padded: bank-conflict-free fragment reads
    int b = blockIdx.x;
    int m = b >> 3, K = b & 7;
    int tid = threadIdx.x;
    const float* src = (m == 0) ? Wf1 : (m == 1) ? Wf2 : (m == 2) ? Wc1 : Wb1;

    // load 16 rows x 128 cols fp32, fully coalesced (2 float4/thread)
    #pragma unroll
    for (int i = 0; i < 2; i++) {
        int e = tid + i * 256;
        int r = e >> 5, c4 = e & 31;
        int gr = K * 16 + r;
        float4 v = make_float4(0.f, 0.f, 0.f, 0.f);
        if (m != 0 || gr < 68) v = ((const float4*)src)[gr * 32 + c4];
        *(float4*)&ws[r][c4 * 4] = v;
    }
    __syncthreads();

    // two fragment uint4 per thread (slices s and s+8)
    int lane = tid & 31, s = tid >> 5;
    int ql = lane & 3, gid = lane >> 2;
    int k0 = 2 * ql;
    #pragma unroll
    for (int h = 0; h < 2; h++) {
        int ss = s + h * 8;
        int n = ss * 8 + gid;
        float v0 = ws[k0][n],     v1 = ws[k0 + 1][n];
        float v2 = ws[k0 + 8][n], v3 = ws[k0 + 9][n];
        uint32_t bh0, bl0, bh1, bl1;
        split2(v0, v1, bh0, bl0);
        split2(v2, v3, bh1, bl1);
        g_bfrag[((m * 8 + K) * 16 + ss) * 32 + lane] = make_uint4(bh0, bh1, bl0, bl1);
    }
}

// one layer: B frags direct from global (8 LDG.128/warp), A frags via ldmatrix
template<int KS>
__device__ __forceinline__ void mma_layer(float acc[3][4],
                                          uint32_t aH, uint32_t aL,
                                          const uint4* __restrict__ frag,
                                          int lr, int lc, int lane)
{
    uint4 B[KS];
    #pragma unroll
    for (int K = 0; K < KS; K++) B[K] = frag[K * 512 + lane];
    uint32_t base = (uint32_t)(lr * WP + lc * 2);
    #pragma unroll
    for (int K = 0; K < KS; K++) {
        uint32_t ah[4], al[4];
        ldm4(ah, aH + base + K * 32);
        ldm4(al, aL + base + K * 32);
        mma_bf16(acc[0], ah, B[K].x, B[K].y);
        mma_bf16(acc[1], ah, B[K].z, B[K].w);
        mma_bf16(acc[2], al, B[K].x, B[K].y);
    }
}

// bias+relu -> bf16 hi/lo act buffer (8-col slice); reset accs
__device__ __forceinline__ void epi_act(float acc[3][4], const float* __restrict__ bias,
                                        char* smem, int offH, int offL,
                                        int w, int lane)
{
    int r0 = lane >> 2, ql = lane & 3;
    int c = w * 8 + 2 * ql;
    float2 b = *(const float2*)(bias + c);
    float v0 = fmaxf(acc[0][0] + acc[1][0] + acc[2][0] + b.x, 0.f);
    float v1 = fmaxf(acc[0][1] + acc[1][1] + acc[2][1] + b.y, 0.f);
    float v2 = fmaxf(acc[0][2] + acc[1][2] + acc[2][2] + b.x, 0.f);
    float v3 = fmaxf(acc[0][3] + acc[1][3] + acc[2][3] + b.y, 0.f);
    uint32_t h0, l0, h1, l1;
    split2(v0, v1, h0, l0);
    split2(v2, v3, h1, l1);
    *(uint32_t*)(smem + offH + r0 * WP + c * 2)       = h0;
    *(uint32_t*)(smem + offL + r0 * WP + c * 2)       = l0;
    *(uint32_t*)(smem + offH + (r0 + 8) * WP + c * 2) = h1;
    *(uint32_t*)(smem + offL + (r0 + 8) * WP + c * 2) = l1;
    #pragma unroll
    for (int p = 0; p < 3; p++)
        acc[p][0] = acc[p][1] = acc[p][2] = acc[p][3] = 0.f;
}

__global__ __launch_bounds__(NTHR, 1) void mlp_kernel(
    const float* __restrict__ x,
    const float* __restrict__ budget,
    const float* __restrict__ emb_id, const float* __restrict__ emb_period,
    const float* __restrict__ emb_time,
    const float* __restrict__ bf1, const float* __restrict__ bf2,
    const float* __restrict__ bc1, const float* __restrict__ Wc2,
    const float* __restrict__ bc2,
    const float* __restrict__ bb1, const float* __restrict__ Wb2,
    const float* __restrict__ bb2,
    float* __restrict__ out)
{
    extern __shared__ char smem[];
    float* smf = (float*)smem;
    const int tid  = threadIdx.x;
    const int w    = tid >> 5;
    const int lane = tid & 31;
    const int lr   = lane & 15;
    const int lc   = (lane >> 4) * 8;
    const int r0l  = lane >> 2;
    const int ql   = lane & 3;
    const int row0 = blockIdx.x * RPB;
    const uint32_t smb = (uint32_t)__cvta_generic_to_shared(smem);
    const uint4* fragW = g_bfrag + w * 32;   // + m*4096 per layer, + K*512 per kstep

    // ======== PDL-independent prologue (runs while convert_kernel finishes) ====
    if (tid < 48) {
        int r = tid / 3, c = tid - r * 3;
        ((int*)(smem + OIX))[r * 3 + c] = (int)x[(row0 + r) * XCOLS + c];
    }
    // budget prefetch -> registers (hides behind the MLP)
    const float4* bud4 = (const float4*)budget + row0 * 128;
    float4 pf[4];
    #pragma unroll
    for (int it = 0; it < 4; it++) pf[it] = bud4[tid + it * NTHR];

    // zero E hi/lo (covers zero-pad cols 68..135); 544 uint4
    if (tid < 544) ((uint4*)(smem + E_H))[tid] = make_uint4(0, 0, 0, 0);
    if (tid < 32)  ((uint4*)(smem + E_H))[512 + tid] = make_uint4(0, 0, 0, 0);

    // wc2bar from Wc2 (harness input — independent of convert) + biases
    if (tid < 128) {
        float s[6] = {0, 0, 0, 0, 0, 0};
        const float4* w4 = (const float4*)(Wc2 + tid * 48);
        #pragma unroll
        for (int v = 0; v < 12; v++) {
            float4 f = w4[v];
            s[(v * 4 + 0) % 6] += f.x; s[(v * 4 + 1) % 6] += f.y;
            s[(v * 4 + 2) % 6] += f.z; s[(v * 4 + 3) % 6] += f.w;
        }
        #pragma unroll
        for (int k = 0; k < 6; k++) smf[OW2 / 4 + tid * 8 + k] = s[k] * 0.125f;
        smf[OW2 / 4 + tid * 8 + 6] = 0.f; smf[OW2 / 4 + tid * 8 + 7] = 0.f;
    } else if (tid < 256) {
        int t = tid - 128;
        smf[OB1 / 4 + t] = bf1[t];
        smf[OB2 / 4 + t] = bf2[t];
        smf[OB3 / 4 + t] = bc1[t];
        smf[OB4 / 4 + t] = bb1[t];
        smf[OWB / 4 + t] = Wb2[t];
    } else if (tid < 262) {
        int t = tid - 256;
        float s = 0.f;
        #pragma unroll
        for (int j = 0; j < 8; j++) s += bc2[j * 6 + t];
        smf[OBC / 4 + t] = s * 0.125f;
    } else if (tid == 262) {
        smf[OBC / 4 + 6] = bb2[0];
    }
    __syncthreads();   // E zeros + indices visible

    // emb fill: row = tid>>5, cols lane, lane+32, lane+64 (div-free)
    {
        const int* ix = (const int*)(smem + OIX);
        int r = tid >> 5;
        int i0 = ix[r * 3 + 0], i1 = ix[r * 3 + 1], i2 = ix[r * 3 + 2];
        #pragma unroll
        for (int jj = 0; jj < 3; jj++) {
            int c = lane + jj * 32;
            if (c < 68) {
                float v;
                if      (c < 8)  v = emb_id    [i1 * 8  + c];
                else if (c < 16) v = emb_period[i0 * 8  + (c - 8)];
                else if (c < 32) v = emb_time  [i2 * 16 + (c - 16)];
                else             v = x[(row0 + r) * XCOLS + 3 + (c - 32)];
                __nv_bfloat16 h = __float2bfloat16(v);
                __nv_bfloat16 l = __float2bfloat16(v - __bfloat162float(h));
                *(__nv_bfloat16*)(smem + E_H + r * WP + c * 2) = h;
                *(__nv_bfloat16*)(smem + E_L + r * WP + c * 2) = l;
            }
        }
    }
    __syncthreads();   // emb + OW2 + biases visible

    // ======== wait for convert_kernel's fragment weights ========
    cudaGridDependencySynchronize();

    float acc[3][4];
    #pragma unroll
    for (int p = 0; p < 3; p++)
        acc[p][0] = acc[p][1] = acc[p][2] = acc[p][3] = 0.f;

    // ---- L1: E x Wf1 -> actA ----
    mma_layer<5>(acc, smb + E_H, smb + E_L, fragW, lr, lc, lane);
    epi_act(acc, smf + OB1 / 4, smem, AAH, AAL, w, lane);
    __syncthreads();

    // ---- L2: actA x Wf2 -> actB ----
    mma_layer<8>(acc, smb + AAH, smb + AAL, fragW + 4096, lr, lc, lane);
    epi_act(acc, smf + OB2 / 4, smem, ABH, ABL, w, lane);
    __syncthreads();

    // ---- L3: actB x Wc1 -> cbar partials (fragment-direct) ----
    mma_layer<8>(acc, smb + ABH, smb + ABL, fragW + 2 * 4096, lr, lc, lane);
    {
        int c0 = w * 8 + 2 * ql;
        float2 b = *(const float2*)(smf + OB3 / 4 + c0);
        float v00 = fmaxf(acc[0][0] + acc[1][0] + acc[2][0] + b.x, 0.f);
        float v01 = fmaxf(acc[0][1] + acc[1][1] + acc[2][1] + b.y, 0.f);
        float v10 = fmaxf(acc[0][2] + acc[1][2] + acc[2][2] + b.x, 0.f);
        float v11 = fmaxf(acc[0][3] + acc[1][3] + acc[2][3] + b.y, 0.f);
        const float* w0p = smf + OW2 / 4 + c0 * 8;
        const float* w1p = w0p + 8;
        float p0[6], p1[6];
        #pragma unroll
        for (int k = 0; k < 6; k++) {
            p0[k] = v00 * w0p[k] + v01 * w1p[k];
            p1[k] = v10 * w0p[k] + v11 * w1p[k];
        }
        #pragma unroll
        for (int k = 0; k < 6; k++) {
            p0[k] += __shfl_xor_sync(0xffffffff, p0[k], 1);
            p0[k] += __shfl_xor_sync(0xffffffff, p0[k], 2);
            p1[k] += __shfl_xor_sync(0xffffffff, p1[k], 1);
            p1[k] += __shfl_xor_sync(0xffffffff, p1[k], 2);
        }
        if (ql == 0) {
            float* d0 = smf + OPC / 4 + (w * 16 + r0l) * 6;
            float* d1 = smf + OPC / 4 + (w * 16 + r0l + 8) * 6;
            #pragma unroll
            for (int k = 0; k < 6; k++) { d0[k] = p0[k]; d1[k] = p1[k]; }
        }
        #pragma unroll
        for (int p = 0; p < 3; p++)
            acc[p][0] = acc[p][1] = acc[p][2] = acc[p][3] = 0.f;
    }
    // NO barrier: L4 re-reads the unchanged actB smem; OPC consumed after next sync

    // ---- L4: actB x Wb1 -> sbase partials ----
    mma_layer<8>(acc, smb + ABH, smb + ABL, fragW + 3 * 4096, lr, lc, lane);
    {
        int c0 = w * 8 + 2 * ql;
        float2 b  = *(const float2*)(smf + OB4 / 4 + c0);
        float2 wv = *(const float2*)(smf + OWB / 4 + c0);
        float s0 = fmaxf(acc[0][0] + acc[1][0] + acc[2][0] + b.x, 0.f) * wv.x
                 + fmaxf(acc[0][1] + acc[1][1] + acc[2][1] + b.y, 0.f) * wv.y;
        float s1 = fmaxf(acc[0][2] + acc[1][2] + acc[2][2] + b.x, 0.f) * wv.x
                 + fmaxf(acc[0][3] + acc[1][3] + acc[2][3] + b.y, 0.f) * wv.y;
        s0 += __shfl_xor_sync(0xffffffff, s0, 1);
        s0 += __shfl_xor_sync(0xffffffff, s0, 2);
        s1 += __shfl_xor_sync(0xffffffff, s1, 1);
        s1 += __shfl_xor_sync(0xffffffff, s1, 2);
        if (ql == 0) {
            smf[OPB / 4 + w * 16 + r0l]     = s0;
            smf[OPB / 4 + w * 16 + r0l + 8] = s1;
        }
    }
    __syncthreads();   // OPC + OPB visible

    // ---- fused combine + cubic (48 threads) + sbase combine (16 threads) ----
    if (tid < 48) {
        int rb = tid / 3, m = tid - rb * 3;
        float cb[4];
        #pragma unroll
        for (int j = 0; j < 4; j++) {
            float s = smf[OBC / 4 + m + j];
            #pragma unroll
            for (int ww = 0; ww < 16; ww++)
                s += smf[OPC / 4 + (ww * 16 + rb) * 6 + m + j];
            cb[j] = s;
        }
        float c0 = cb[0], c1 = cb[1], c2 = cb[2], c3 = cb[3];
        const float k6 = 1.f / 6.f;
        float A0 = (c0 + 4.f * c1 + c2) * k6;
        float A1 = (c2 - c0) * 0.5f;
        float A2 = (c0 - 2.f * c1 + c2) * 0.5f;
        float A3 = (c3 - c0 + 3.f * (c1 - c2)) * k6;
        float d  = 1.5f - (float)m;
        float B0 = A0 + d * (A1 + d * (A2 + d * A3));
        float B1 = 1.5f * (A1 + d * (2.f * A2 + 3.f * A3 * d));
        float B2 = 2.25f * (A2 + 3.f * A3 * d);
        float B3 = 3.375f * A3;
        ((float4*)(smem + OCF))[rb * 4 + m] = make_float4(B0, B1, B2, B3);
    } else if (tid < 64) {
        int rb = tid - 48;
        float s = smf[OBC / 4 + 6];
        #pragma unroll
        for (int ww = 0; ww < 16; ww++)
            s += smf[OPB / 4 + ww * 16 + rb];
        smf[OSB / 4 + rb] = s;
    }
    __syncthreads();

    // ---- budget phase: data already in pf[] registers ----
    float4* out4 = (float4*)out + row0 * 128;
    const float4* cb4 = (const float4*)(smem + OCF);
    #pragma unroll
    for (int it = 0; it < 4; it++) {
        int q = tid + it * NTHR;
        int row = q >> 7;
        float4 bv = pf[it];
        float sb = smf[OSB / 4 + row];
        float xs[4] = {bv.x, bv.y, bv.z, bv.w};
        float o[4];
        #pragma unroll
        for (int e = 0; e < 4; e++) {
            float X = xs[e];
            float tp = fmaf(X, 1.5f, 1.5f);
            int m = min((int)tp, 2);
            float4 B = cb4[row * 4 + m];
            float sp = fmaf(fmaf(fmaf(B.w, X, B.z), X, B.y), X, B.x);
            float u = X * X;
            float P = fmaf(u, fmaf(u, fmaf(u, fmaf(u, 2.1357286e-5f, -2.1081349e-4f),
                                           2.0833333e-3f), -2.0833333e-2f), 0.25f);
            float sil = X * fmaf(X, P, 0.5f);
            o[e] = sb * (sil + sp);
        }
        out4[q] = make_float4(o[0], o[1], o[2], o[3]);
    }
}

extern "C" void kernel_launch(void* const* d_in, const int* in_sizes, int n_in,
                              void* d_out, int out_size)
{
    const float* x          = (const float*)d_in[0];
    const float* budget     = (const float*)d_in[1];
    const float* emb_id     = (const float*)d_in[2];
    const float* emb_period = (const float*)d_in[3];
    const float* emb_time   = (const float*)d_in[4];
    const float* Wf1 = (const float*)d_in[5];
    const float* bf1 = (const float*)d_in[6];
    const float* Wf2 = (const float*)d_in[7];
    const float* bf2 = (const float*)d_in[8];
    const float* Wc1 = (const float*)d_in[9];
    const float* bc1 = (const float*)d_in[10];
    const float* Wc2 = (const float*)d_in[11];
    const float* bc2 = (const float*)d_in[12];
    // d_in[13..16] = Ws1/bs1/Ws2/bs2 : unused in reference output
    const float* Wb1 = (const float*)d_in[17];
    const float* bb1 = (const float*)d_in[18];
    const float* Wb2 = (const float*)d_in[19];
    const float* bb2 = (const float*)d_in[20];

    cudaFuncSetAttribute(mlp_kernel, cudaFuncAttributeMaxDynamicSharedMemorySize, MLP_SMEM);

    convert_kernel<<<32, 256>>>(Wf1, Wf2, Wc1, Wb1);

    // PDL launch: mlp starts while convert drains; prologue runs pre-sync
    cudaLaunchConfig_t cfg = {};
    cfg.gridDim = dim3(NCTA);
    cfg.blockDim = dim3(NTHR);
    cfg.dynamicSmemBytes = MLP_SMEM;
    cfg.stream = 0;
    cudaLaunchAttribute attrs[1];
    attrs[0].id = cudaLaunchAttributeProgrammaticStreamSerialization;
    attrs[0].val.programmaticStreamSerializationAllowed = 1;
    cfg.attrs = attrs;
    cfg.numAttrs = 1;
    cudaLaunchKernelEx(&cfg, mlp_kernel,
                       x, budget, emb_id, emb_period, emb_time,
                       bf1, bf2, bc1, Wc2, bc2, bb1, Wb2, bb2, (float*)d_out);
}